// round 17
// baseline (speedup 1.0000x reference)
#include <cuda_runtime.h>
#include <cuda_fp16.h>
#include <cstdint>

// SelfAttention: out = softmax((xWq)(xWk)^T / 64) @ (xWv)
// N=8192, d_model=256, d_k=d_v=64, fp32.
// R17 = R14 attn (proven best; R15/R16 attn changes regressed and are
// reverted) + proj overhaul:
//  - cvt_kernel pre-packs x -> fp16x2 (g_X2) and W -> fp16x2 in B-fragment
//    layout (g_Wt[col][k2]), so proj's hot loop is pure LDS.32 + mma
//    (no packh2, half the staging bytes).
//  - attn: fp16 m16n8k16, Q-frag smem stash, NSPLIT=6, max-free softmax,
//    ex2.f32 + FADD l (R14 exact).

#define NTOK 8192
#define NE   256
#define DH   64
#define BR   128
#define BC   64
#define NSPLIT 6

// attn smem (bytes): Qstash | K0 | K1 | V0 | V1 (K/V rows: 72 halves = 144B)
#define OFFB_K0 16384
#define OFFB_K1 25600
#define OFFB_V0 34816
#define OFFB_V1 44032
#define SMEM_BYTES 53248
#define ROWU 36               // K/V row stride in u32

// proj smem: per buffer {x16[64][36] u32, wt[64][36] u32}; double-buffered
#define PCH (64 * 36)                 // u32 per 64x(32+pad) tile
#define PSMEM_BYTES (4 * PCH * 4 * 2) // 2 bufs x 2 tiles x PCH u32 = 73728

__device__ uint32_t g_X2[NTOK * (NE / 2)];   // fp16x2-packed x rows
__device__ uint32_t g_Wt[3 * DH * (NE / 2)]; // W^T packed: [y][col][k2]
__device__ uint32_t g_Q2[NTOK * 32];   // fp16x2-packed Q, pre-scaled log2e/64
__device__ uint32_t g_K2[NTOK * 32];   // fp16x2-packed K
__device__ __half   g_Vt[DH * NTOK];   // fp16 V transposed [d][tok]
__device__ float g_Op[(size_t)NSPLIT * NTOK * DH];
__device__ float g_Lp[NSPLIT * NTOK];

__device__ __forceinline__ float ex2(float f) {
    float r;
    asm("ex2.approx.ftz.f32 %0, %1;" : "=f"(r) : "f"(f));
    return r;
}
// pack {lo, hi} floats -> fp16x2 (RN). First PTX src is the HIGH half.
__device__ __forceinline__ uint32_t packh2(float lo, float hi) {
    uint32_t r;
    asm("cvt.rn.f16x2.f32 %0, %1, %2;" : "=r"(r) : "f"(hi), "f"(lo));
    return r;
}

__device__ __forceinline__ void mma16(float* d, const uint32_t* a,
                                      uint32_t b0, uint32_t b1) {
    asm volatile(
        "mma.sync.aligned.m16n8k16.row.col.f32.f16.f16.f32 "
        "{%0,%1,%2,%3}, {%4,%5,%6,%7}, {%8,%9}, {%0,%1,%2,%3};"
        : "+f"(d[0]), "+f"(d[1]), "+f"(d[2]), "+f"(d[3])
        : "r"(a[0]), "r"(a[1]), "r"(a[2]), "r"(a[3]), "r"(b0), "r"(b1));
}

__device__ __forceinline__ uint32_t smem_u32(const void* p) {
    uint32_t a;
    asm("{ .reg .u64 t; cvta.to.shared.u64 t, %1; cvt.u32.u64 %0, t; }"
        : "=r"(a) : "l"(p));
    return a;
}
__device__ __forceinline__ void cp16(uint32_t saddr, const void* g) {
    asm volatile("cp.async.cg.shared.global [%0], [%1], 16;"
                 :: "r"(saddr), "l"(g) : "memory");
}

// ---------------------------------------------------------------------------
// Kernel 0: convert. Blocks 0..2047: x -> g_X2 (float4 -> 2 u32 each thread).
// Blocks 2048..2050: W -> g_Wt (B-fragment layout, 32 u32/thread).
// ---------------------------------------------------------------------------
__global__ __launch_bounds__(256) void cvt_kernel(
    const float* __restrict__ x, const float* __restrict__ Wq,
    const float* __restrict__ Wk, const float* __restrict__ Wv)
{
    const int b = blockIdx.x;
    if (b < 2048) {
        // x: 8192*256 floats = 512K float4; thread handles one float4.
        const int t = b * 256 + threadIdx.x;
        float4 v = *(const float4*)&x[(size_t)t * 4];
        uint2 o;
        o.x = packh2(v.x, v.y);
        o.y = packh2(v.z, v.w);
        *(uint2*)&g_X2[t * 2] = o;
    } else {
        // W: 3 * 64 cols * 128 k2 = 24576 u32 over 768 threads -> 32 each.
        const int base = (b - 2048) * 256 + threadIdx.x;   // 0..767
        const float* Ws[3] = { Wq, Wk, Wv };
#pragma unroll
        for (int i = 0; i < 32; i++) {
            int j = base * 32 + i;                 // 0..24575
            int y = j >> 13;
            int col = (j >> 7) & 63;
            int k2 = j & 127;
            const float* W = Ws[y];
            g_Wt[y * 8192 + col * 128 + k2] =
                packh2(W[(2 * k2) * DH + col], W[(2 * k2 + 1) * DH + col]);
        }
    }
}

// ---------------------------------------------------------------------------
// Kernel 1: projection from pre-packed fp16 operands. 128 threads, fp16
// m16n8k16; hot loop is LDS.32 + mma only. cp.async double-buffered.
// ---------------------------------------------------------------------------
__global__ __launch_bounds__(128) void proj_kernel()
{
    extern __shared__ uint32_t psw[];

    const int tid  = threadIdx.x;
    const int w    = tid >> 5;
    const int lane = tid & 31;
    const int g    = lane >> 2;
    const int c    = lane & 3;
    const int rb   = blockIdx.x * 64;
    const int y    = blockIdx.y;
    const uint32_t sb = smem_u32(psw);

    const uint32_t* Wt = g_Wt + y * 8192;

    // buffer b: x16 at u32 offset b*2*PCH, wt at b*2*PCH + PCH
    auto stage = [&](int kc4, int b) {
#pragma unroll
        for (int i = 0; i < 4; i++) {
            int idx = tid + 128 * i;
            int row = idx >> 3, ch = idx & 7;     // row/col 0..63, 16B chunk
            cp16(sb + (b * 2 * PCH + row * 36) * 4 + ch * 16,
                 &g_X2[(rb + row) * 128 + kc4 * 32 + ch * 4]);
            cp16(sb + ((b * 2 + 1) * PCH + row * 36) * 4 + ch * 16,
                 &Wt[row * 128 + kc4 * 32 + ch * 4]);
        }
        asm volatile("cp.async.commit_group;" ::: "memory");
    };

    float acc[8][4];
#pragma unroll
    for (int n = 0; n < 8; n++)
#pragma unroll
        for (int k = 0; k < 4; k++) acc[n][k] = 0.f;

    stage(0, 0);
    for (int kc4 = 0; kc4 < 4; kc4++) {
        const int b = kc4 & 1;
        if (kc4 < 3) {
            stage(kc4 + 1, b ^ 1);
            asm volatile("cp.async.wait_group 1;" ::: "memory");
        } else {
            asm volatile("cp.async.wait_group 0;" ::: "memory");
        }
        __syncthreads();

        const uint32_t* xs = psw + b * 2 * PCH;
        const uint32_t* ws = xs + PCH;
#pragma unroll
        for (int kk = 0; kk < 4; kk++) {
            uint32_t a[4];
            a[0] = xs[(16 * w + g) * 36 + 8 * kk + c];
            a[1] = xs[(16 * w + g + 8) * 36 + 8 * kk + c];
            a[2] = xs[(16 * w + g) * 36 + 8 * kk + c + 4];
            a[3] = xs[(16 * w + g + 8) * 36 + 8 * kk + c + 4];
#pragma unroll
            for (int n = 0; n < 8; n++) {
                uint32_t b0 = ws[(8 * n + g) * 36 + 8 * kk + c];
                uint32_t b1 = ws[(8 * n + g) * 36 + 8 * kk + c + 4];
                mma16(acc[n], a, b0, b1);
            }
        }
        __syncthreads();
    }

    const int r0 = rb + 16 * w + g;
    if (y == 2) {
        // V transposed: g_Vt[d][token], fp16 RN
#pragma unroll
        for (int n = 0; n < 8; n++) {
            int col = 8 * n + 2 * c;
            g_Vt[col * NTOK + r0]           = __float2half_rn(acc[n][0]);
            g_Vt[(col + 1) * NTOK + r0]     = __float2half_rn(acc[n][1]);
            g_Vt[col * NTOK + r0 + 8]       = __float2half_rn(acc[n][2]);
            g_Vt[(col + 1) * NTOK + r0 + 8] = __float2half_rn(acc[n][3]);
        }
    } else {
        uint32_t* out = (y == 0) ? g_Q2 : g_K2;
        const float sc = (y == 0) ? (1.44269504088896341f / 64.0f) : 1.0f;
#pragma unroll
        for (int n = 0; n < 8; n++) {
            out[r0 * 32 + 4 * n + c]       = packh2(acc[n][0] * sc, acc[n][1] * sc);
            out[(r0 + 8) * 32 + 4 * n + c] = packh2(acc[n][2] * sc, acc[n][3] * sc);
        }
    }
}

// ---------------------------------------------------------------------------
// Kernel 2: fp16 partial flash attention (R14 verbatim). grid (64, 6),
// 128 threads = 4 warps, 32 query rows/warp. Q frags in smem stash.
// ---------------------------------------------------------------------------
__global__ __launch_bounds__(128) void attn_partial(int dummy)
{
    extern __shared__ uint32_t smw[];

    const int tid  = threadIdx.x;
    const int w    = tid >> 5;
    const int lane = tid & 31;
    const int g    = lane >> 2;
    const int c    = lane & 3;
    const int qb   = blockIdx.x * BR;
    const int p    = blockIdx.y;
    const int t0   = p * 21 + min(p, 2);          // 22,22,21,21,21,21 tiles
    const int tcnt = 21 + (p < 2 ? 1 : 0);
    const uint32_t sb = smem_u32(smw);

    // ---- build Q fragment stash (fragment-order; warp-private region)
#pragma unroll
    for (int f = 0; f < 2; f++) {
        const int row = qb + 32 * w + 16 * f + g;
#pragma unroll
        for (int kk = 0; kk < 4; kk++) {
            uint4 v;
            v.x = g_Q2[row * 32 + 8 * kk + c];
            v.y = g_Q2[(row + 8) * 32 + 8 * kk + c];
            v.z = g_Q2[row * 32 + 8 * kk + c + 4];
            v.w = g_Q2[(row + 8) * 32 + 8 * kk + c + 4];
            *(uint4*)&smw[w * 1024 + (f * 4 + kk) * 128 + lane * 4] = v;
        }
    }
    __syncwarp();

    float o[2][8][4];
#pragma unroll
    for (int f = 0; f < 2; f++)
#pragma unroll
        for (int n = 0; n < 8; n++)
#pragma unroll
            for (int k = 0; k < 4; k++) o[f][n][k] = 0.f;
    float l00 = 0.f, l01 = 0.f, l10 = 0.f, l11 = 0.f;

    auto stage = [&](int t, int b) {
        const int kb = (t0 + t) * BC;
        const uint32_t dK = sb + (b ? OFFB_K1 : OFFB_K0);
        const uint32_t dV = sb + (b ? OFFB_V1 : OFFB_V0);
#pragma unroll
        for (int i = 0; i < 4; i++) {
            int idx = tid + 128 * i;
            int row = idx >> 3, ch = idx & 7;      // row 0..63, 16B chunk 0..7
            cp16(dK + row * 144 + ch * 16, &g_K2[(kb + row) * 32 + ch * 4]);
            cp16(dV + row * 144 + ch * 16, &g_Vt[row * NTOK + kb + ch * 8]);
        }
        asm volatile("cp.async.commit_group;" ::: "memory");
    };

    stage(0, 0);

    for (int t = 0; t < tcnt; t++) {
        const int b = t & 1;
        if (t + 1 < tcnt) {
            stage(t + 1, b ^ 1);
            asm volatile("cp.async.wait_group 1;" ::: "memory");
        } else {
            asm volatile("cp.async.wait_group 0;" ::: "memory");
        }
        __syncthreads();

        const uint32_t* k32 = smw + (b ? OFFB_K1 / 4 : OFFB_K0 / 4);
        const uint32_t* v32 = smw + (b ? OFFB_V1 / 4 : OFFB_V0 / 4);

        // ---- S' = (Q*log2e/64) @ K^T ; Q frags reloaded per kk (LDS.128)
        float s[2][8][4];
#pragma unroll
        for (int f = 0; f < 2; f++)
#pragma unroll
            for (int j = 0; j < 8; j++)
#pragma unroll
                for (int k = 0; k < 4; k++) s[f][j][k] = 0.f;
#pragma unroll
        for (int kk = 0; kk < 4; kk++) {
            const uint32_t* st = &smw[w * 1024 + kk * 128 + lane * 4];
            uint4 A0 = *(const uint4*)st;
            uint4 A1 = *(const uint4*)(st + 512);   // f=1 block
#pragma unroll
            for (int j = 0; j < 8; j++) {
                uint32_t b0 = k32[(8 * j + g) * ROWU + 8 * kk + c];
                uint32_t b1 = k32[(8 * j + g) * ROWU + 8 * kk + c + 4];
                mma16(s[0][j], (const uint32_t*)&A0, b0, b1);
                mma16(s[1][j], (const uint32_t*)&A1, b0, b1);
            }
        }

        // ---- max-free softmax: P = 2^(S'). RN pack unbiased; l sums raw e.
        uint32_t ps[2][8][2];
#pragma unroll
        for (int f = 0; f < 2; f++) {
#pragma unroll
            for (int j = 0; j < 8; j++) {
                float e0 = ex2(s[f][j][0]);
                float e1 = ex2(s[f][j][1]);
                float e2 = ex2(s[f][j][2]);
                float e3 = ex2(s[f][j][3]);
                if (f == 0) { l00 += e0 + e1; l01 += e2 + e3; }
                else        { l10 += e0 + e1; l11 += e2 + e3; }
                ps[f][j][0] = packh2(e0, e1);
                ps[f][j][1] = packh2(e2, e3);
            }
        }

        // ---- O += P @ V  (A = packed P regs; B = Vt rows)
#pragma unroll
        for (int kk = 0; kk < 4; kk++) {
            uint32_t a0[4] = { ps[0][2 * kk][0], ps[0][2 * kk][1],
                               ps[0][2 * kk + 1][0], ps[0][2 * kk + 1][1] };
            uint32_t a1[4] = { ps[1][2 * kk][0], ps[1][2 * kk][1],
                               ps[1][2 * kk + 1][0], ps[1][2 * kk + 1][1] };
#pragma unroll
            for (int n = 0; n < 8; n++) {
                uint32_t b0 = v32[(8 * n + g) * ROWU + 8 * kk + c];
                uint32_t b1 = v32[(8 * n + g) * ROWU + 8 * kk + c + 4];
                mma16(o[0][n], a0, b0, b1);
                mma16(o[1][n], a1, b0, b1);
            }
        }
        __syncthreads();   // all warps done with this buffer before restage
    }

    // ---- quad row sums; emit partial (unnormalized O + l)
    l00 += __shfl_xor_sync(0xffffffffu, l00, 1);
    l00 += __shfl_xor_sync(0xffffffffu, l00, 2);
    l01 += __shfl_xor_sync(0xffffffffu, l01, 1);
    l01 += __shfl_xor_sync(0xffffffffu, l01, 2);
    l10 += __shfl_xor_sync(0xffffffffu, l10, 1);
    l10 += __shfl_xor_sync(0xffffffffu, l10, 2);
    l11 += __shfl_xor_sync(0xffffffffu, l11, 1);
    l11 += __shfl_xor_sync(0xffffffffu, l11, 2);

    float* op = g_Op + (size_t)p * NTOK * DH;
#pragma unroll
    for (int f = 0; f < 2; f++) {
        const int r0 = qb + 32 * w + 16 * f + g;
#pragma unroll
        for (int n = 0; n < 8; n++) {
            int col = 8 * n + 2 * c;
            *(float2*)&op[(size_t)r0 * DH + col] =
                make_float2(o[f][n][0], o[f][n][1]);
            *(float2*)&op[(size_t)(r0 + 8) * DH + col] =
                make_float2(o[f][n][2], o[f][n][3]);
        }
    }
    if (c == 0) {
        const int r0 = qb + 32 * w;
        g_Lp[p * NTOK + r0 + g]      = l00;
        g_Lp[p * NTOK + r0 + 8 + g]  = l01;
        g_Lp[p * NTOK + r0 + 16 + g] = l10;
        g_Lp[p * NTOK + r0 + 24 + g] = l11;
    }
}

// ---------------------------------------------------------------------------
// Kernel 3: merge the 6 partials (additive), float4 vectorized.
// ---------------------------------------------------------------------------
__global__ __launch_bounds__(256) void reduce_kernel(float* __restrict__ out)
{
    const int i4 = blockIdx.x * 256 + threadIdx.x;
    const int idx = i4 * 4;
    const int r = idx >> 6;

    float denom = 0.f;
#pragma unroll
    for (int p = 0; p < NSPLIT; p++) denom += g_Lp[p * NTOK + r];
    const float inv = 1.0f / denom;

    float4 v = make_float4(0.f, 0.f, 0.f, 0.f);
#pragma unroll
    for (int p = 0; p < NSPLIT; p++) {
        float4 a = *(const float4*)&g_Op[(size_t)p * NTOK * DH + idx];
        v.x += a.x; v.y += a.y; v.z += a.z; v.w += a.w;
    }
    v.x *= inv; v.y *= inv; v.z *= inv; v.w *= inv;
    *(float4*)&out[idx] = v;
}

extern "C" void kernel_launch(void* const* d_in, const int* in_sizes, int n_in,
                              void* d_out, int out_size) {
    const float* x  = (const float*)d_in[0];
    const float* Wq = (const float*)d_in[1];
    const float* Wk = (const float*)d_in[2];
    const float* Wv = (const float*)d_in[3];
    float* out = (float*)d_out;

    // Idempotent attribute sets (not stream ops; capture-safe).
    cudaFuncSetAttribute(proj_kernel,
                         cudaFuncAttributeMaxDynamicSharedMemorySize,
                         PSMEM_BYTES);
    cudaFuncSetAttribute(attn_partial,
                         cudaFuncAttributeMaxDynamicSharedMemorySize,
                         SMEM_BYTES);

    cvt_kernel<<<2051, 256>>>(x, Wq, Wk, Wv);
    proj_kernel<<<dim3(NTOK / 64, 3), 128, PSMEM_BYTES>>>();
    attn_partial<<<dim3(NTOK / BR, NSPLIT), 128, SMEM_BYTES>>>(0);
    reduce_kernel<<<(NTOK * DH) / 1024, 256>>>(out);
}